// round 16
// baseline (speedup 1.0000x reference)
#include <cuda_runtime.h>
#include <cuda_bf16.h>
#include <math.h>

// ---------------------------------------------------------------------------
// GraphEncoder: 4-layer GATv2 on N=50000 nodes, E=800000 edges (+self loops).
//   - CSR over dst per launch (hist -> fused scan -> scatter).
//   - Layer 0: x0 = emb[node_type] has 3 distinct rows -> xl0/xr0 are 3x128
//     tables; edge pass gathers from shared memory.
//   - Layers 1-3: gemm2 (xl = x@Wl, xr = x@Wr) with packed fma.rn.f32x2.
//   - Edge pass: persistent warps + global ticket. SPLIT-WARP layout: each
//     lane owns 8 floats, a 16-lane half covers a full row, the two halves
//     process two edges at once (logit reduction = 2 shuffle rounds for H=4).
//     NO-MAX softmax with MUFU ex2; odd tail via the exact 0.5-weight trick;
//     fused bias+residual+LayerNorm+ReLU epilogue.
// ---------------------------------------------------------------------------

#define NN 50000
#define EE 800000
#define SCAN_BLK 512

__device__ float g_bufA[(size_t)NN * 128];
__device__ float g_bufB[(size_t)NN * 128];
__device__ float g_xl[(size_t)NN * 128];
__device__ float g_xr[(size_t)NN * 128];
__device__ int   g_cnt[NN];
__device__ int   g_off[NN + 1];
__device__ int   g_cur[NN];
__device__ int   g_csr[EE];
__device__ int   g_bsum[SCAN_BLK];
__device__ float g_wp[8 * 16384];   // packed weights, slots 2..7 (layers 1-3)
__device__ float g_tl[384];         // layer-0 xl table [3][128]
__device__ float g_tr[384];         // layer-0 xr table [3][128]
__device__ int   g_tick[4];         // work tickets, one per edge launch

// ---------------------------------------------------------------------------
__device__ __forceinline__ unsigned long long ffma2(unsigned long long a,
                                                    unsigned long long b,
                                                    unsigned long long c) {
    unsigned long long d;
    asm("fma.rn.f32x2 %0, %1, %2, %3;" : "=l"(d) : "l"(a), "l"(b), "l"(c));
    return d;
}

__device__ __forceinline__ float pairsum(unsigned long long v) {
    float lo = __uint_as_float((unsigned)(v & 0xffffffffull));
    float hi = __uint_as_float((unsigned)(v >> 32));
    return lo + hi;
}

// guaranteed single-MUFU exp2 (exp2f without fast-math is a slow polynomial)
__device__ __forceinline__ float ex2(float x) {
    float y;
    asm("ex2.approx.ftz.f32 %0, %1;" : "=f"(y) : "f"(x));
    return y;
}

// ---------------------------------------------------------------------------
// prep: zero cnt, reset tickets, pack W (layers 1-3), build layer-0 tables.
__global__ void prep_kernel(const float* __restrict__ W1l, const float* __restrict__ W1r,
                            const float* __restrict__ W2l, const float* __restrict__ W2r,
                            const float* __restrict__ W3l, const float* __restrict__ W3r,
                            float* __restrict__ wp,
                            const float* __restrict__ emb,
                            const float* __restrict__ Wl0, const float* __restrict__ Wr0,
                            float* __restrict__ tl, float* __restrict__ tr,
                            int* __restrict__ tick, int* __restrict__ cnt, int n) {
    int gtid = blockIdx.x * blockDim.x + threadIdx.x;
    int gs = gridDim.x * blockDim.x;
    for (int i = gtid; i < n; i += gs) cnt[i] = 0;
    if (gtid < 4) tick[gtid] = 0;
    if (gtid < 3 * 16384) {
        int li = gtid / 16384, r = gtid - li * 16384;
        const float* Wl = (li == 0) ? W1l : (li == 1) ? W2l : W3l;
        const float* Wr = (li == 0) ? W1r : (li == 1) ? W2r : W3r;
        int k = r >> 7, c = r & 127;
        int o = (k >> 1) * 256 + c * 2 + (k & 1);
        float* dst = wp + (size_t)(2 * (li + 1)) * 16384;
        dst[o]         = Wl[r];
        dst[16384 + o] = Wr[r];
    } else if (gtid < 3 * 16384 + 384) {
        int t = gtid - 3 * 16384;
        int type = t >> 7, col = t & 127;
        float sl = 0.f, sr = 0.f;
#pragma unroll
        for (int k = 0; k < 16; k++) {
            float e = emb[type * 16 + k];
            sl = fmaf(e, Wl0[k * 128 + col], sl);
            sr = fmaf(e, Wr0[k * 128 + col], sr);
        }
        tl[t] = sl;
        tr[t] = sr;
    }
}

__global__ void hist_kernel(int* __restrict__ cnt, const int* __restrict__ dst, int E) {
    int e = blockIdx.x * blockDim.x + threadIdx.x;
    if (e < E) atomicAdd(&cnt[dst[e]], 1);
}

__global__ void block_sum_kernel(const int* __restrict__ cnt, int* __restrict__ bsum, int n) {
    __shared__ int sh[SCAN_BLK];
    int i = blockIdx.x * SCAN_BLK + threadIdx.x;
    sh[threadIdx.x] = (i < n) ? cnt[i] : 0;
    __syncthreads();
    for (int d = SCAN_BLK / 2; d > 0; d >>= 1) {
        if (threadIdx.x < d) sh[threadIdx.x] += sh[threadIdx.x + d];
        __syncthreads();
    }
    if (threadIdx.x == 0) bsum[blockIdx.x] = sh[0];
}

// fused: each block derives its own prefix (sum of bsum[0..bid)) then scans.
__global__ void block_scan_kernel(const int* __restrict__ cnt, const int* __restrict__ bsum,
                                  int* __restrict__ off, int* __restrict__ cur, int n) {
    __shared__ int sh[SCAN_BLK];
    int t = threadIdx.x;
    int pv = (t < blockIdx.x) ? bsum[t] : 0;
    sh[t] = pv;
    __syncthreads();
    for (int d = SCAN_BLK / 2; d > 0; d >>= 1) {
        if (t < d) sh[t] += sh[t + d];
        __syncthreads();
    }
    int bpre = sh[0];
    __syncthreads();
    int i = blockIdx.x * SCAN_BLK + t;
    int v = (i < n) ? cnt[i] : 0;
    sh[t] = v;
    __syncthreads();
    for (int d = 1; d < SCAN_BLK; d <<= 1) {
        int u = (t >= d) ? sh[t - d] : 0;
        __syncthreads();
        sh[t] += u;
        __syncthreads();
    }
    int excl = sh[t] - v + bpre;
    if (i < n) { off[i] = excl; cur[i] = excl; }
    if (i == n - 1) off[n] = excl + v;
}

__global__ void scatter_kernel(int* __restrict__ cur, const int* __restrict__ src,
                               const int* __restrict__ dst, int* __restrict__ csr, int E) {
    int e = blockIdx.x * blockDim.x + threadIdx.x;
    if (e < E) {
        int d = dst[e];
        int p = atomicAdd(&cur[d], 1);
        csr[p] = src[e];
    }
}

// ---------------------------------------------------------------------------
// gemm2: xl = x @ Wl, xr = x @ Wr via packed f32x2 FMA. K = 128.
__global__ void __launch_bounds__(128, 3)
gemm2_kernel(const float* __restrict__ x,
             const float* __restrict__ Wpl, const float* __restrict__ Wpr,
             float* __restrict__ xl, float* __restrict__ xr, int n) {
    const int K = 128;
    int w = (blockIdx.x * blockDim.x + threadIdx.x) >> 5;
    int lane = threadIdx.x & 31;
    int node0 = (w >> 1) * 8;
    if (node0 >= n) return;
    int col = ((w & 1) << 6) + lane * 2;

    unsigned long long aL[8][2], aR[8][2];
#pragma unroll
    for (int j = 0; j < 8; j++) {
        aL[j][0] = aL[j][1] = 0ull;
        aR[j][0] = aR[j][1] = 0ull;
    }

    const float* xp = x + (size_t)node0 * K;
    const float* wl = Wpl + col * 2;
    const float* wr = Wpr + col * 2;

    for (int k0 = 0; k0 < K; k0 += 4) {
        ulonglong2 xv[8];
#pragma unroll
        for (int j = 0; j < 8; j++)
            xv[j] = *(const ulonglong2*)(xp + (size_t)j * K + k0);
#pragma unroll
        for (int s = 0; s < 2; s++) {
            int k2 = (k0 >> 1) + s;
            ulonglong2 wlv = *(const ulonglong2*)(wl + k2 * 256);
            ulonglong2 wrv = *(const ulonglong2*)(wr + k2 * 256);
#pragma unroll
            for (int j = 0; j < 8; j++) {
                unsigned long long xb = s ? xv[j].y : xv[j].x;
                aL[j][0] = ffma2(wlv.x, xb, aL[j][0]);
                aL[j][1] = ffma2(wlv.y, xb, aL[j][1]);
                aR[j][0] = ffma2(wrv.x, xb, aR[j][0]);
                aR[j][1] = ffma2(wrv.y, xb, aR[j][1]);
            }
        }
    }
#pragma unroll
    for (int j = 0; j < 8; j++) {
        float2 rl = make_float2(pairsum(aL[j][0]), pairsum(aL[j][1]));
        float2 rr = make_float2(pairsum(aR[j][0]), pairsum(aR[j][1]));
        *(float2*)(xl + (size_t)(node0 + j) * 128 + col) = rl;
        *(float2*)(xr + (size_t)(node0 + j) * 128 + col) = rr;
    }
}

// ---------------------------------------------------------------------------
// Persistent split-warp edge pass. Lane layout: lane = half*16 + hl;
// lane owns floats [hl*8, hl*8+8) of a row; half 0/1 process different items.
// Items: idx 0 = self loop, idx 1..deg = csr edges. Odd tail: both halves
// process it with e *= 0.5 (exact), the cross-half combine restores 1x.
// H==4: head = hl>>2, logit reduce = xor {1,2}. H==1: reduce = xor {1,2,4,8}.
template <int H, bool NT>
__global__ void gat_edge_kernel(const float* __restrict__ xl, const float* __restrict__ xr,
                                const int* __restrict__ ntyp,
                                const float* __restrict__ xres,  // nullptr if no residual
                                const float* __restrict__ att, const float* __restrict__ bias,
                                const float* __restrict__ lng, const float* __restrict__ lnb,
                                const int* __restrict__ off, const int* __restrict__ csr,
                                float* __restrict__ out, int* __restrict__ tick, int n) {
    __shared__ float s_tl[NT ? 384 : 1];
    __shared__ float s_tr[NT ? 384 : 1];
    if (NT) {
        for (int i = threadIdx.x; i < 384; i += blockDim.x) {
            s_tl[i] = xl[i];
            s_tr[i] = xr[i];
        }
        __syncthreads();
    }

    const unsigned FULL = 0xffffffffu;
    int lane = threadIdx.x & 31;
    int half = lane >> 4;
    int hl   = lane & 15;
    int f_base = hl * 8;           // 8 floats per lane; 16 lanes cover 128
    constexpr int RED = (H == 4) ? 4 : 16;   // lanes per logit group
    const float LOG2E = 1.4426950408889634f;

    float4 att0 = *(const float4*)(att + f_base);
    float4 att1 = *(const float4*)(att + f_base + 4);
    att0.x *= LOG2E; att0.y *= LOG2E; att0.z *= LOG2E; att0.w *= LOG2E;
    att1.x *= LOG2E; att1.y *= LOG2E; att1.z *= LOG2E; att1.w *= LOG2E;
    float4 bv0 = *(const float4*)(bias + f_base);
    float4 bv1 = *(const float4*)(bias + f_base + 4);
    float4 gv0 = *(const float4*)(lng + f_base);
    float4 gv1 = *(const float4*)(lng + f_base + 4);
    float4 bb0 = *(const float4*)(lnb + f_base);
    float4 bb1 = *(const float4*)(lnb + f_base + 4);

    for (;;) {
        int base;
        if (lane == 0) base = atomicAdd(tick, 4);
        base = __shfl_sync(FULL, base, 0);
        if (base >= n) break;
        int nmax = min(base + 4, n);

        for (int node = base; node < nmax; node++) {
            float4 xr0, xr1;
            if (NT) {
                int ty = ntyp[node] * 128;
                xr0 = *(const float4*)(s_tr + ty + f_base);
                xr1 = *(const float4*)(s_tr + ty + f_base + 4);
            } else {
                xr0 = *(const float4*)(xr + (size_t)node * 128 + f_base);
                xr1 = *(const float4*)(xr + (size_t)node * 128 + f_base + 4);
            }

            int beg = off[node];
            int totalItems = off[node + 1] - beg + 1;   // + self loop (idx 0)

            float z = 0.f;
            float4 a0 = make_float4(0.f, 0.f, 0.f, 0.f);
            float4 a1 = make_float4(0.f, 0.f, 0.f, 0.f);

            // load this half's item row (8 floats)
            auto loadItem = [&](int idx, float4& lo, float4& hi) {
                int s = (idx == 0) ? node : csr[beg + idx - 1];
                if (NT) {
                    int ty = ntyp[s] * 128;
                    lo = *(const float4*)(s_tl + ty + f_base);
                    hi = *(const float4*)(s_tl + ty + f_base + 4);
                } else {
                    lo = *(const float4*)(xl + (size_t)s * 128 + f_base);
                    hi = *(const float4*)(xl + (size_t)s * 128 + f_base + 4);
                }
            };
            // leaky + dot over this lane's 8 features (att pre-scaled)
            auto part8 = [&](const float4& lo, const float4& hi) -> float {
                float t, p;
                t = lo.x + xr0.x; p  = fmaxf(t, 0.2f * t) * att0.x;
                t = lo.y + xr0.y; p += fmaxf(t, 0.2f * t) * att0.y;
                t = lo.z + xr0.z; p += fmaxf(t, 0.2f * t) * att0.z;
                t = lo.w + xr0.w; p += fmaxf(t, 0.2f * t) * att0.w;
                t = hi.x + xr1.x; p += fmaxf(t, 0.2f * t) * att1.x;
                t = hi.y + xr1.y; p += fmaxf(t, 0.2f * t) * att1.y;
                t = hi.z + xr1.z; p += fmaxf(t, 0.2f * t) * att1.z;
                t = hi.w + xr1.w; p += fmaxf(t, 0.2f * t) * att1.w;
                return p;
            };

            int i = 0;
            // ---- 2 pairs (4 items) per iteration: MLP ~4 rows in flight ----
            for (; i + 4 <= totalItems; i += 4) {
                float4 loA, hiA, loB, hiB;
                loadItem(i + half, loA, hiA);
                loadItem(i + 2 + half, loB, hiB);
                float pA = part8(loA, hiA);
                float pB = part8(loB, hiB);
#pragma unroll
                for (int o = 1; o < RED; o <<= 1) {
                    pA += __shfl_xor_sync(FULL, pA, o);
                    pB += __shfl_xor_sync(FULL, pB, o);
                }
                float eA = ex2(pA), eB = ex2(pB);
                z += eA + eB;
                a0.x = fmaf(eB, loB.x, fmaf(eA, loA.x, a0.x));
                a0.y = fmaf(eB, loB.y, fmaf(eA, loA.y, a0.y));
                a0.z = fmaf(eB, loB.z, fmaf(eA, loA.z, a0.z));
                a0.w = fmaf(eB, loB.w, fmaf(eA, loA.w, a0.w));
                a1.x = fmaf(eB, hiB.x, fmaf(eA, hiA.x, a1.x));
                a1.y = fmaf(eB, hiB.y, fmaf(eA, hiA.y, a1.y));
                a1.z = fmaf(eB, hiB.z, fmaf(eA, hiA.z, a1.z));
                a1.w = fmaf(eB, hiB.w, fmaf(eA, hiA.w, a1.w));
            }
            // ---- one remaining full pair ----
            if (i + 2 <= totalItems) {
                float4 lo, hi;
                loadItem(i + half, lo, hi);
                float p = part8(lo, hi);
#pragma unroll
                for (int o = 1; o < RED; o <<= 1)
                    p += __shfl_xor_sync(FULL, p, o);
                float e = ex2(p);
                z += e;
                a0.x = fmaf(e, lo.x, a0.x); a0.y = fmaf(e, lo.y, a0.y);
                a0.z = fmaf(e, lo.z, a0.z); a0.w = fmaf(e, lo.w, a0.w);
                a1.x = fmaf(e, hi.x, a1.x); a1.y = fmaf(e, hi.y, a1.y);
                a1.z = fmaf(e, hi.z, a1.z); a1.w = fmaf(e, hi.w, a1.w);
                i += 2;
            }
            // ---- odd tail: both halves process it at half weight (exact) ----
            if (i < totalItems) {
                float4 lo, hi;
                loadItem(i, lo, hi);
                float p = part8(lo, hi);
#pragma unroll
                for (int o = 1; o < RED; o <<= 1)
                    p += __shfl_xor_sync(FULL, p, o);
                float e = 0.5f * ex2(p);
                z += e;
                a0.x = fmaf(e, lo.x, a0.x); a0.y = fmaf(e, lo.y, a0.y);
                a0.z = fmaf(e, lo.z, a0.z); a0.w = fmaf(e, lo.w, a0.w);
                a1.x = fmaf(e, hi.x, a1.x); a1.y = fmaf(e, hi.y, a1.y);
                a1.z = fmaf(e, hi.z, a1.z); a1.w = fmaf(e, hi.w, a1.w);
            }

            // ---- combine the two halves (features duplicated afterwards) ----
            z += __shfl_xor_sync(FULL, z, 16);
            a0.x += __shfl_xor_sync(FULL, a0.x, 16);
            a0.y += __shfl_xor_sync(FULL, a0.y, 16);
            a0.z += __shfl_xor_sync(FULL, a0.z, 16);
            a0.w += __shfl_xor_sync(FULL, a0.w, 16);
            a1.x += __shfl_xor_sync(FULL, a1.x, 16);
            a1.y += __shfl_xor_sync(FULL, a1.y, 16);
            a1.z += __shfl_xor_sync(FULL, a1.z, 16);
            a1.w += __shfl_xor_sync(FULL, a1.w, 16);

            float invz = 1.f / z;
            float4 o0, o1;
            o0.x = a0.x * invz + bv0.x; o0.y = a0.y * invz + bv0.y;
            o0.z = a0.z * invz + bv0.z; o0.w = a0.w * invz + bv0.w;
            o1.x = a1.x * invz + bv1.x; o1.y = a1.y * invz + bv1.y;
            o1.z = a1.z * invz + bv1.z; o1.w = a1.w * invz + bv1.w;
            if (xres) {
                float4 r0 = *(const float4*)(xres + (size_t)node * 128 + f_base);
                float4 r1 = *(const float4*)(xres + (size_t)node * 128 + f_base + 4);
                o0.x += r0.x; o0.y += r0.y; o0.z += r0.z; o0.w += r0.w;
                o1.x += r1.x; o1.y += r1.y; o1.z += r1.z; o1.w += r1.w;
            }
            // LayerNorm over 128 dims; values duplicated across halves -> /256
            float s = (o0.x + o0.y + o0.z + o0.w) + (o1.x + o1.y + o1.z + o1.w);
#pragma unroll
            for (int o = 1; o < 32; o <<= 1) s += __shfl_xor_sync(FULL, s, o);
            float mean = s * (1.0f / 256.0f);
            float d0x = o0.x - mean, d0y = o0.y - mean, d0z = o0.z - mean, d0w = o0.w - mean;
            float d1x = o1.x - mean, d1y = o1.y - mean, d1z = o1.z - mean, d1w = o1.w - mean;
            float sq = (d0x * d0x + d0y * d0y + d0z * d0z + d0w * d0w)
                     + (d1x * d1x + d1y * d1y + d1z * d1z + d1w * d1w);
#pragma unroll
            for (int o = 1; o < 32; o <<= 1) sq += __shfl_xor_sync(FULL, sq, o);
            float r = rsqrtf(sq * (1.0f / 256.0f) + 1e-5f);
            o0.x = fmaxf(d0x * r * gv0.x + bb0.x, 0.f);
            o0.y = fmaxf(d0y * r * gv0.y + bb0.y, 0.f);
            o0.z = fmaxf(d0z * r * gv0.z + bb0.z, 0.f);
            o0.w = fmaxf(d0w * r * gv0.w + bb0.w, 0.f);
            o1.x = fmaxf(d1x * r * gv1.x + bb1.x, 0.f);
            o1.y = fmaxf(d1y * r * gv1.y + bb1.y, 0.f);
            o1.z = fmaxf(d1z * r * gv1.z + bb1.z, 0.f);
            o1.w = fmaxf(d1w * r * gv1.w + bb1.w, 0.f);
            if (half == 0) {
                *(float4*)(out + (size_t)node * 128 + f_base)     = o0;
                *(float4*)(out + (size_t)node * 128 + f_base + 4) = o1;
            }
        }
    }
}

// ---------------------------------------------------------------------------
extern "C" void kernel_launch(void* const* d_in, const int* in_sizes, int n_in,
                              void* d_out, int out_size) {
    const int*   node_types = (const int*)d_in[0];
    const int*   ei         = (const int*)d_in[1];
    const float* emb        = (const float*)d_in[2];
    const float* lng        = (const float*)d_in[19];
    const float* lnb        = (const float*)d_in[20];

    int n = in_sizes[0];
    int E = in_sizes[1] / 2;
    const int* src = ei;
    const int* dst = ei + E;

    float *bufA, *bufB, *xl, *xr, *wp, *tl, *tr;
    int *cnt, *off, *cur, *csr, *bsum, *tick;
    cudaGetSymbolAddress((void**)&bufA, g_bufA);
    cudaGetSymbolAddress((void**)&bufB, g_bufB);
    cudaGetSymbolAddress((void**)&xl,   g_xl);
    cudaGetSymbolAddress((void**)&xr,   g_xr);
    cudaGetSymbolAddress((void**)&cnt,  g_cnt);
    cudaGetSymbolAddress((void**)&off,  g_off);
    cudaGetSymbolAddress((void**)&cur,  g_cur);
    cudaGetSymbolAddress((void**)&csr,  g_csr);
    cudaGetSymbolAddress((void**)&bsum, g_bsum);
    cudaGetSymbolAddress((void**)&wp,   g_wp);
    cudaGetSymbolAddress((void**)&tl,   g_tl);
    cudaGetSymbolAddress((void**)&tr,   g_tr);
    cudaGetSymbolAddress((void**)&tick, g_tick);

    prep_kernel<<<(3 * 16384 + 384 + 255) / 256, 256>>>(
        (const float*)d_in[7], (const float*)d_in[8],
        (const float*)d_in[11], (const float*)d_in[12],
        (const float*)d_in[15], (const float*)d_in[16], wp,
        emb, (const float*)d_in[3], (const float*)d_in[4], tl, tr,
        tick, cnt, n);

    int nb = (n + SCAN_BLK - 1) / SCAN_BLK;
    hist_kernel<<<(E + 255) / 256, 256>>>(cnt, dst, E);
    block_sum_kernel<<<nb, SCAN_BLK>>>(cnt, bsum, n);
    block_scan_kernel<<<nb, SCAN_BLK>>>(cnt, bsum, off, cur, n);
    scatter_kernel<<<(E + 255) / 256, 256>>>(cur, src, dst, csr, E);

    int gemm_warps  = ((n + 7) / 8) * 2;
    int gemm_blocks = (gemm_warps + 3) / 4;
    int edge_blocks = 148 * 6;

    // ---- layer 0 ----
    gat_edge_kernel<4, true><<<edge_blocks, 256>>>(tl, tr, node_types, nullptr,
                                                   (const float*)d_in[5], (const float*)d_in[6],
                                                   lng + 0, lnb + 0, off, csr, bufB, tick + 0, n);
    // ---- layer 1 ----
    gemm2_kernel<<<gemm_blocks, 128>>>(bufB, wp + 2 * 16384, wp + 3 * 16384, xl, xr, n);
    gat_edge_kernel<4, false><<<edge_blocks, 256>>>(xl, xr, nullptr, bufB,
                                                    (const float*)d_in[9], (const float*)d_in[10],
                                                    lng + 128, lnb + 128, off, csr, bufA, tick + 1, n);
    // ---- layer 2 ----
    gemm2_kernel<<<gemm_blocks, 128>>>(bufA, wp + 4 * 16384, wp + 5 * 16384, xl, xr, n);
    gat_edge_kernel<4, false><<<edge_blocks, 256>>>(xl, xr, nullptr, bufA,
                                                    (const float*)d_in[13], (const float*)d_in[14],
                                                    lng + 256, lnb + 256, off, csr, bufB, tick + 2, n);
    // ---- layer 3 ----
    gemm2_kernel<<<gemm_blocks, 128>>>(bufB, wp + 6 * 16384, wp + 7 * 16384, xl, xr, n);
    gat_edge_kernel<1, false><<<edge_blocks, 256>>>(xl, xr, nullptr, bufB,
                                                    (const float*)d_in[17], (const float*)d_in[18],
                                                    lng + 384, lnb + 384, off, csr, (float*)d_out, tick + 3, n);
}